// round 5
// baseline (speedup 1.0000x reference)
#include <cuda_runtime.h>

#define MSA 256
#define SEQ 384
#define DM  256
#define DH  32
#define DP  128
#define EPSV 1e-5f

// Scratch (device globals -- no allocations allowed)
__device__ float g_left[MSA * SEQ * DH];    // (m, i, c)
__device__ float g_right[MSA * SEQ * DH];   // (m, j, d)
__device__ float g_count[SEQ * SEQ];        // (i, j)

// ---------------------------------------------------------------------------
// Kernel 1: LayerNorm + left/right projections (+ bias, mask)
// Block = 64 threads handles 8 rows (row = m*SEQ + i).
// Phase A: 8 threads per row compute LN stats + write xn to smem.
// Phase B: each thread owns one output column (32 left + 32 right),
//          caches weight chunks in registers, accumulates all 8 rows.
// NOTE: mask is int32 (harness converts jax bool -> int32).
// ---------------------------------------------------------------------------
__global__ void ln_proj_kernel(const float* __restrict__ x,
                               const int* __restrict__ mask,
                               const float* __restrict__ ln_g,
                               const float* __restrict__ ln_b,
                               const float* __restrict__ wl,
                               const float* __restrict__ bl,
                               const float* __restrict__ wr,
                               const float* __restrict__ br)
{
    __shared__ float xns[8][DM];

    const int t = threadIdx.x;          // 0..63
    const int r = t >> 3;               // row-in-block 0..7
    const int lane8 = t & 7;
    const int row0 = blockIdx.x * 8;
    const int row = row0 + r;

    const float4* xrow = (const float4*)(x + (size_t)row * DM);

    float4 v[8];
    float s = 0.f, ss = 0.f;
#pragma unroll
    for (int kk = 0; kk < 8; kk++) {
        v[kk] = xrow[kk * 8 + lane8];
        s  += v[kk].x + v[kk].y + v[kk].z + v[kk].w;
        ss += v[kk].x * v[kk].x + v[kk].y * v[kk].y
            + v[kk].z * v[kk].z + v[kk].w * v[kk].w;
    }
    // butterfly reduce within the 8-lane group
#pragma unroll
    for (int off = 4; off >= 1; off >>= 1) {
        s  += __shfl_xor_sync(0xffffffffu, s,  off);
        ss += __shfl_xor_sync(0xffffffffu, ss, off);
    }
    const float mu   = s * (1.0f / DM);
    const float var  = ss * (1.0f / DM) - mu * mu;
    const float rstd = rsqrtf(var + EPSV);

    const float4* g4 = (const float4*)ln_g;
    const float4* b4 = (const float4*)ln_b;
#pragma unroll
    for (int kk = 0; kk < 8; kk++) {
        float4 gg = g4[kk * 8 + lane8];
        float4 bb = b4[kk * 8 + lane8];
        float4 o;
        o.x = (v[kk].x - mu) * rstd * gg.x + bb.x;
        o.y = (v[kk].y - mu) * rstd * gg.y + bb.y;
        o.z = (v[kk].z - mu) * rstd * gg.z + bb.z;
        o.w = (v[kk].w - mu) * rstd * gg.w + bb.w;
        ((float4*)&xns[r][0])[kk * 8 + lane8] = o;
    }
    __syncthreads();

    // ---- Phase B: projections ----
    const float* W  = (t < DH) ? wl : wr;
    const float* Bv = (t < DH) ? bl : br;
    const int c = t & 31;

    float acc[8];
#pragma unroll
    for (int rr = 0; rr < 8; rr++) acc[rr] = 0.f;

    for (int kc = 0; kc < DM; kc += 16) {
        float wreg[16];
#pragma unroll
        for (int kk = 0; kk < 16; kk++)
            wreg[kk] = W[(kc + kk) * DH + c];
#pragma unroll
        for (int rr = 0; rr < 8; rr++) {
            float a = acc[rr];
#pragma unroll
            for (int kk = 0; kk < 16; kk++)
                a += xns[rr][kc + kk] * wreg[kk];
            acc[rr] = a;
        }
    }

    const float bias = Bv[c];
    float* dst = (t < DH) ? g_left : g_right;
#pragma unroll
    for (int rr = 0; rr < 8; rr++) {
        const int rw = row0 + rr;
        const float mf = (mask[rw] != 0) ? 1.0f : 0.0f;
        dst[(size_t)rw * DH + c] = (acc[rr] + bias) * mf;
    }
}

// ---------------------------------------------------------------------------
// Kernel 2: pairwise mask count: count[i,j] = sum_m mask[m,i]*mask[m,j]
// mask is int32.
// ---------------------------------------------------------------------------
__global__ void count_kernel(const int* __restrict__ mask)
{
    const int i = blockIdx.x;
    const int j0 = threadIdx.x;            // 0..127
    float acc0 = 0.f, acc1 = 0.f, acc2 = 0.f;
    for (int m = 0; m < MSA; m++) {
        const int* mrow = mask + m * SEQ;
        const float mi = (mrow[i] != 0) ? 1.0f : 0.0f;
        acc0 += mi * ((mrow[j0]       != 0) ? 1.0f : 0.0f);
        acc1 += mi * ((mrow[j0 + 128] != 0) ? 1.0f : 0.0f);
        acc2 += mi * ((mrow[j0 + 256] != 0) ? 1.0f : 0.0f);
    }
    g_count[i * SEQ + j0]       = acc0;
    g_count[i * SEQ + j0 + 128] = acc1;
    g_count[i * SEQ + j0 + 256] = acc2;
}

// ---------------------------------------------------------------------------
// Kernel 3: fused outer-product GEMM (K=m=256) + wo projection + normalize.
// Each CTA: 4x4 (i,j) tile = 16 pairs; 256 threads; thread = (pair, 8c x 8d).
// Then stage the 16x1024 outer tile in smem and do out = outer @ wo + bo,
// divided by (count + eps).
// ---------------------------------------------------------------------------
__global__ void __launch_bounds__(256)
fused_outer_kernel(const float* __restrict__ wo,
                   const float* __restrict__ bo,
                   float* __restrict__ out)
{
    extern __shared__ float smem[];      // 16384 floats (64 KB)
    float* Ls = smem;                    // [16][128]
    float* Rs = smem + 2048;             // [16][128]

    const int tid = threadIdx.x;
    const int i0 = blockIdx.x * 4;
    const int j0 = blockIdx.y * 4;
    const int pair = tid >> 4;           // 0..15
    const int q    = tid & 15;
    const int ii = pair >> 2, jj = pair & 3;
    const int c0 = (q & 3) * 8;          // 0,8,16,24
    const int d0 = (q >> 2) * 8;

    float acc[8][8];
#pragma unroll
    for (int a = 0; a < 8; a++)
#pragma unroll
        for (int b = 0; b < 8; b++) acc[a][b] = 0.f;

    const float4* gl4 = (const float4*)g_left;
    const float4* gr4 = (const float4*)g_right;

    for (int m0 = 0; m0 < MSA; m0 += 16) {
        // load 16 x 128 tiles of L and R (float4, coalesced)
#pragma unroll
        for (int rr = 0; rr < 2; rr++) {
            const int idx = tid + rr * 256;        // 0..511
            const int km  = idx >> 5;
            const int iw  = (idx >> 3) & 3;
            const int c4  = idx & 7;
            ((float4*)Ls)[idx] = gl4[((size_t)(m0 + km) * SEQ + i0 + iw) * 8 + c4];
            ((float4*)Rs)[idx] = gr4[((size_t)(m0 + km) * SEQ + j0 + iw) * 8 + c4];
        }
        __syncthreads();

#pragma unroll
        for (int km = 0; km < 16; km++) {
            float l[8], rv[8];
            *(float4*)&l[0]  = ((const float4*)Ls)[km * 32 + ii * 8 + (c0 >> 2)];
            *(float4*)&l[4]  = ((const float4*)Ls)[km * 32 + ii * 8 + (c0 >> 2) + 1];
            *(float4*)&rv[0] = ((const float4*)Rs)[km * 32 + jj * 8 + (d0 >> 2)];
            *(float4*)&rv[4] = ((const float4*)Rs)[km * 32 + jj * 8 + (d0 >> 2) + 1];
#pragma unroll
            for (int a = 0; a < 8; a++)
#pragma unroll
                for (int b = 0; b < 8; b++)
                    acc[a][b] += l[a] * rv[b];
        }
        __syncthreads();
    }

    // ---- stage outer tile to smem: accS[pair][c*32 + d], 16x1024 floats ----
    float* accS = smem;
#pragma unroll
    for (int a = 0; a < 8; a++) {
        float4 w0, w1;
        w0.x = acc[a][0]; w0.y = acc[a][1]; w0.z = acc[a][2]; w0.w = acc[a][3];
        w1.x = acc[a][4]; w1.y = acc[a][5]; w1.z = acc[a][6]; w1.w = acc[a][7];
        const int base = pair * 256 + (((c0 + a) * 32 + d0) >> 2);
        ((float4*)accS)[base]     = w0;
        ((float4*)accS)[base + 1] = w1;
    }
    __syncthreads();

    // ---- GEMM2: out[pair][p] = sum_cd accS[pair][cd] * wo[cd][p] ----
    const int pbase = q * 8;
    float o[8];
#pragma unroll
    for (int k = 0; k < 8; k++) o[k] = 0.f;

    const float4* wo4 = (const float4*)wo;
    const float4* aS4 = (const float4*)accS;
    for (int cd = 0; cd < DH * DH; cd += 4) {
        float av[4];
        *(float4*)av = aS4[pair * 256 + (cd >> 2)];
#pragma unroll
        for (int u = 0; u < 4; u++) {
            float wv[8];
            *(float4*)&wv[0] = wo4[(cd + u) * 32 + (pbase >> 2)];
            *(float4*)&wv[4] = wo4[(cd + u) * 32 + (pbase >> 2) + 1];
#pragma unroll
            for (int k = 0; k < 8; k++)
                o[k] += av[u] * wv[k];
        }
    }

    const int i = i0 + ii, j = j0 + jj;
    const float inv = 1.0f / (g_count[i * SEQ + j] + EPSV);
    float bv[8];
    *(float4*)&bv[0] = ((const float4*)bo)[pbase >> 2];
    *(float4*)&bv[4] = ((const float4*)bo)[(pbase >> 2) + 1];

    float4 r0, r1;
    r0.x = (o[0] + bv[0]) * inv; r0.y = (o[1] + bv[1]) * inv;
    r0.z = (o[2] + bv[2]) * inv; r0.w = (o[3] + bv[3]) * inv;
    r1.x = (o[4] + bv[4]) * inv; r1.y = (o[5] + bv[5]) * inv;
    r1.z = (o[6] + bv[6]) * inv; r1.w = (o[7] + bv[7]) * inv;

    float4* outp = (float4*)(out + ((size_t)(i * SEQ + j)) * DP + pbase);
    outp[0] = r0;
    outp[1] = r1;
}

// ---------------------------------------------------------------------------
extern "C" void kernel_launch(void* const* d_in, const int* in_sizes, int n_in,
                              void* d_out, int out_size)
{
    const float* x    = (const float*)d_in[0];
    const int*   mk   = (const int*)d_in[1];
    const float* ln_g = (const float*)d_in[2];
    const float* ln_b = (const float*)d_in[3];
    const float* wl   = (const float*)d_in[4];
    const float* bl   = (const float*)d_in[5];
    const float* wr   = (const float*)d_in[6];
    const float* br   = (const float*)d_in[7];
    const float* wo   = (const float*)d_in[8];
    const float* bo   = (const float*)d_in[9];
    float* out        = (float*)d_out;

    cudaFuncSetAttribute(fused_outer_kernel,
                         cudaFuncAttributeMaxDynamicSharedMemorySize, 65536);

    ln_proj_kernel<<<(MSA * SEQ) / 8, 64>>>(x, mk, ln_g, ln_b, wl, bl, wr, br);
    count_kernel<<<SEQ, 128>>>(mk);
    fused_outer_kernel<<<dim3(SEQ / 4, SEQ / 4), 256, 65536>>>(wo, bo, out);
}

// round 8
// speedup vs baseline: 3.3121x; 3.3121x over previous
#include <cuda_runtime.h>
#include <cuda_bf16.h>
#include <cstdint>

#define MSA 256
#define SEQ 384
#define DM  256
#define DH  32
#define DP  128
#define EPSV 1e-5f

#define AROWS 12288          // SEQ*DH rows for GEMM1 operands
#define PAIRS (SEQ*SEQ)      // 147456

// ---------------- scratch (device globals; no allocations allowed) ----------
// L'/R': row = i*32+c (resp j*32+d), cols 0..255 = hi(m), 256..511 = lo(m)
__device__ __nv_bfloat16 g_l[AROWS * 512];
__device__ __nv_bfloat16 g_r[AROWS * 512];
// outer: row = pair (i*384+j), cols 0..1023 = hi(cd), 1024..2047 = lo(cd)
__device__ __nv_bfloat16 g_outer[(size_t)PAIRS * 2048];
// wo transposed+split: row = p, cols 0..1023 hi(cd), 1024..2047 lo(cd)
__device__ __nv_bfloat16 g_wo[DP * 2048];
__device__ float g_count[SEQ * SEQ];

// ---------------- helpers ---------------------------------------------------
__device__ __forceinline__ uint32_t smem_u32(const void* p) {
    uint32_t a;
    asm("{ .reg .u64 t; cvta.to.shared.u64 t, %1; cvt.u32.u64 %0, t; }"
        : "=r"(a) : "l"(p));
    return a;
}
__device__ __forceinline__ uint32_t pack_bf16(__nv_bfloat16 a, __nv_bfloat16 b) {
    return (uint32_t)__bfloat16_as_ushort(a) | ((uint32_t)__bfloat16_as_ushort(b) << 16);
}
__device__ __forceinline__ void ldmat_x4(uint32_t* r, uint32_t addr) {
    asm volatile("ldmatrix.sync.aligned.m8n8.x4.shared.b16 {%0,%1,%2,%3}, [%4];"
                 : "=r"(r[0]), "=r"(r[1]), "=r"(r[2]), "=r"(r[3]) : "r"(addr));
}
__device__ __forceinline__ void mma16816(float* c, const uint32_t* a,
                                         uint32_t b0, uint32_t b1) {
    asm volatile(
        "mma.sync.aligned.m16n8k16.row.col.f32.bf16.bf16.f32 "
        "{%0,%1,%2,%3}, {%4,%5,%6,%7}, {%8,%9}, {%0,%1,%2,%3};"
        : "+f"(c[0]), "+f"(c[1]), "+f"(c[2]), "+f"(c[3])
        : "r"(a[0]), "r"(a[1]), "r"(a[2]), "r"(a[3]), "r"(b0), "r"(b1));
}

#define SPAD 40   // smem row pitch in bf16 (32 data + 8 pad)

// ---------------------------------------------------------------------------
// Kernel 1: LayerNorm + projections; writes L'/R' as bf16 hi/lo split in
// GEMM1 operand layout (row = i*32+c, col = m (hi) / 256+m (lo)).
// Block = 64 threads: one i, 8 consecutive m. mask is int32.
// ---------------------------------------------------------------------------
__global__ void ln_proj_kernel(const float* __restrict__ x,
                               const int* __restrict__ mask,
                               const float* __restrict__ ln_g,
                               const float* __restrict__ ln_b,
                               const float* __restrict__ wl,
                               const float* __restrict__ bl,
                               const float* __restrict__ wr,
                               const float* __restrict__ br)
{
    __shared__ float xns[8][DM];

    const int t = threadIdx.x;
    const int r = t >> 3;
    const int lane8 = t & 7;
    const int i  = blockIdx.x >> 5;
    const int m0 = (blockIdx.x & 31) * 8;
    const size_t rowg = (size_t)(m0 + r) * SEQ + i;

    const float4* xrow = (const float4*)(x + rowg * DM);

    float4 v[8];
    float s = 0.f, ss = 0.f;
#pragma unroll
    for (int kk = 0; kk < 8; kk++) {
        v[kk] = xrow[kk * 8 + lane8];
        s  += v[kk].x + v[kk].y + v[kk].z + v[kk].w;
        ss += v[kk].x * v[kk].x + v[kk].y * v[kk].y
            + v[kk].z * v[kk].z + v[kk].w * v[kk].w;
    }
#pragma unroll
    for (int off = 4; off >= 1; off >>= 1) {
        s  += __shfl_xor_sync(0xffffffffu, s,  off);
        ss += __shfl_xor_sync(0xffffffffu, ss, off);
    }
    const float mu   = s * (1.0f / DM);
    const float var  = ss * (1.0f / DM) - mu * mu;
    const float rstd = rsqrtf(var + EPSV);

    const float4* g4 = (const float4*)ln_g;
    const float4* b4 = (const float4*)ln_b;
#pragma unroll
    for (int kk = 0; kk < 8; kk++) {
        float4 gg = g4[kk * 8 + lane8];
        float4 bb = b4[kk * 8 + lane8];
        float4 o;
        o.x = (v[kk].x - mu) * rstd * gg.x + bb.x;
        o.y = (v[kk].y - mu) * rstd * gg.y + bb.y;
        o.z = (v[kk].z - mu) * rstd * gg.z + bb.z;
        o.w = (v[kk].w - mu) * rstd * gg.w + bb.w;
        ((float4*)&xns[r][0])[kk * 8 + lane8] = o;
    }
    __syncthreads();

    const float* W  = (t < DH) ? wl : wr;
    const float* Bv = (t < DH) ? bl : br;
    const int c = t & 31;

    float acc[8];
#pragma unroll
    for (int rr = 0; rr < 8; rr++) acc[rr] = 0.f;

    for (int kc = 0; kc < DM; kc += 16) {
        float wreg[16];
#pragma unroll
        for (int kk = 0; kk < 16; kk++)
            wreg[kk] = W[(kc + kk) * DH + c];
#pragma unroll
        for (int rr = 0; rr < 8; rr++) {
            float a = acc[rr];
#pragma unroll
            for (int kk = 0; kk < 16; kk++)
                a += xns[rr][kc + kk] * wreg[kk];
            acc[rr] = a;
        }
    }

    const float bias = Bv[c];
    uint32_t hw[4], lw[4];
#pragma unroll
    for (int q = 0; q < 4; q++) {
        float vs[2];
#pragma unroll
        for (int h = 0; h < 2; h++) {
            const int rr = q * 2 + h;
            const float mf = (mask[(m0 + rr) * SEQ + i] != 0) ? 1.0f : 0.0f;
            vs[h] = (acc[rr] + bias) * mf;
        }
        __nv_bfloat16 h0 = __float2bfloat16(vs[0]);
        __nv_bfloat16 h1 = __float2bfloat16(vs[1]);
        __nv_bfloat16 l0 = __float2bfloat16(vs[0] - __bfloat162float(h0));
        __nv_bfloat16 l1 = __float2bfloat16(vs[1] - __bfloat162float(h1));
        hw[q] = pack_bf16(h0, h1);
        lw[q] = pack_bf16(l0, l1);
    }
    __nv_bfloat16* dst = ((t < DH) ? g_l : g_r) + ((size_t)(i * 32 + c)) * 512;
    *(uint4*)(dst + m0)       = make_uint4(hw[0], hw[1], hw[2], hw[3]);
    *(uint4*)(dst + 256 + m0) = make_uint4(lw[0], lw[1], lw[2], lw[3]);
}

// ---------------------------------------------------------------------------
// Kernel 2: pairwise mask count (int32 mask)
// ---------------------------------------------------------------------------
__global__ void count_kernel(const int* __restrict__ mask)
{
    const int i = blockIdx.x;
    const int j0 = threadIdx.x;
    float acc0 = 0.f, acc1 = 0.f, acc2 = 0.f;
    for (int m = 0; m < MSA; m++) {
        const int* mrow = mask + m * SEQ;
        const float mi = (mrow[i] != 0) ? 1.0f : 0.0f;
        acc0 += mi * ((mrow[j0]       != 0) ? 1.0f : 0.0f);
        acc1 += mi * ((mrow[j0 + 128] != 0) ? 1.0f : 0.0f);
        acc2 += mi * ((mrow[j0 + 256] != 0) ? 1.0f : 0.0f);
    }
    g_count[i * SEQ + j0]       = acc0;
    g_count[i * SEQ + j0 + 128] = acc1;
    g_count[i * SEQ + j0 + 256] = acc2;
}

// ---------------------------------------------------------------------------
// Kernel 3: transpose+split wo -> g_wo[p][cd hi | cd lo]
// ---------------------------------------------------------------------------
__global__ void wo_prep_kernel(const float* __restrict__ wo)
{
    const int p = blockIdx.x;
    for (int k = threadIdx.x; k < 1024; k += 256) {
        float v = wo[(size_t)k * DP + p];
        __nv_bfloat16 h = __float2bfloat16(v);
        __nv_bfloat16 l = __float2bfloat16(v - __bfloat162float(h));
        g_wo[(size_t)p * 2048 + k]        = h;
        g_wo[(size_t)p * 2048 + 1024 + k] = l;
    }
}

// ---------------------------------------------------------------------------
// GEMM1 (mma.sync bf16): outer = L' x R'^T.
// M=N=12288, extended K' = 768 (hh | hl | lh split combos via column remap).
// CTA 128x128, 8 warps (2x4), warp tile 64x32, K-chunk 32.
// Epilogue: split fp32 accum -> bf16 hi/lo, scatter to g_outer[pair][cd].
// ---------------------------------------------------------------------------
__global__ void __launch_bounds__(256, 2)
gemm1_kernel()
{
    __shared__ __nv_bfloat16 As[128 * SPAD];
    __shared__ __nv_bfloat16 Bs[128 * SPAD];

    const int tid  = threadIdx.x;
    const int wid  = tid >> 5;
    const int lane = tid & 31;
    const int warpM = wid & 1;          // 0..1
    const int warpN = wid >> 1;         // 0..3
    const int aRow0 = blockIdx.x * 128;
    const int bRow0 = blockIdx.y * 128;

    const uint32_t asb = smem_u32(As);

    float acc[4][4][4];
#pragma unroll
    for (int mt = 0; mt < 4; mt++)
#pragma unroll
        for (int nt = 0; nt < 4; nt++)
#pragma unroll
            for (int e = 0; e < 4; e++) acc[mt][nt][e] = 0.f;

    const int lr = tid >> 2;            // 0..63  (load row pair helper)
    const int lj = tid & 3;             // 0..3

    for (int kc = 0; kc < 24; kc++) {
        const int k0 = kc * 32;
        const int colA = (k0 < 256) ? k0 : k0 - 256;
        const int colB = (k0 < 512) ? k0 : k0 - 512;
#pragma unroll
        for (int q = 0; q < 2; q++) {
            const int r = lr + q * 64;
            *(uint4*)&As[r * SPAD + lj * 8] =
                *(const uint4*)&g_l[(size_t)(aRow0 + r) * 512 + colA + lj * 8];
            *(uint4*)&Bs[r * SPAD + lj * 8] =
                *(const uint4*)&g_r[(size_t)(bRow0 + r) * 512 + colB + lj * 8];
        }
        __syncthreads();

#pragma unroll
        for (int ks = 0; ks < 2; ks++) {
            const int kb = ks * 16;
            uint32_t a[4][4];
#pragma unroll
            for (int mt = 0; mt < 4; mt++) {
                const int row = warpM * 64 + mt * 16 + (lane & 15);
                const uint32_t addr =
                    asb + (uint32_t)((row * SPAD + kb + (lane >> 4) * 8) * 2);
                ldmat_x4(a[mt], addr);
            }
#pragma unroll
            for (int nt = 0; nt < 4; nt++) {
                const int n = warpN * 32 + nt * 8 + (lane >> 2);
                const int cb = kb + (lane & 3) * 2;
                const uint32_t b0 = *(const uint32_t*)&Bs[n * SPAD + cb];
                const uint32_t b1 = *(const uint32_t*)&Bs[n * SPAD + cb + 8];
#pragma unroll
                for (int mt = 0; mt < 4; mt++)
                    mma16816(acc[mt][nt], a[mt], b0, b1);
            }
        }
        __syncthreads();
    }

    // Epilogue: scatter hi/lo bf16 to g_outer
#pragma unroll
    for (int mt = 0; mt < 4; mt++) {
#pragma unroll
        for (int nt = 0; nt < 4; nt++) {
            const int rB = bRow0 + warpN * 32 + nt * 8 + (lane & 3) * 2;
            const int jj = rB >> 5, dd = rB & 31;
#pragma unroll
            for (int h = 0; h < 2; h++) {
                const int rA = aRow0 + warpM * 64 + mt * 16 + (lane >> 2) + h * 8;
                const float v0 = acc[mt][nt][h * 2 + 0];
                const float v1 = acc[mt][nt][h * 2 + 1];
                __nv_bfloat16 h0 = __float2bfloat16(v0);
                __nv_bfloat16 h1 = __float2bfloat16(v1);
                __nv_bfloat16 l0 = __float2bfloat16(v0 - __bfloat162float(h0));
                __nv_bfloat16 l1 = __float2bfloat16(v1 - __bfloat162float(h1));
                const size_t pair = (size_t)((rA >> 5) * SEQ + jj);
                const int cd = (rA & 31) * 32 + dd;
                *(uint32_t*)&g_outer[pair * 2048 + cd]        = pack_bf16(h0, h1);
                *(uint32_t*)&g_outer[pair * 2048 + 1024 + cd] = pack_bf16(l0, l1);
            }
        }
    }
}

// ---------------------------------------------------------------------------
// GEMM2 (mma.sync bf16): out = outer x wo^T (+bo, /count).
// M=147456 (pairs), N=128 (p), extended K' = 3072.
// Same tiling as GEMM1. B tile (g_wo) is the full N=128.
// ---------------------------------------------------------------------------
__global__ void __launch_bounds__(256, 2)
gemm2_kernel(const float* __restrict__ bo, float* __restrict__ out)
{
    __shared__ __nv_bfloat16 As[128 * SPAD];
    __shared__ __nv_bfloat16 Bs[128 * SPAD];

    const int tid  = threadIdx.x;
    const int wid  = tid >> 5;
    const int lane = tid & 31;
    const int warpM = wid & 1;
    const int warpN = wid >> 1;
    const size_t pair0 = (size_t)blockIdx.x * 128;

    const uint32_t asb = smem_u32(As);

    float acc[4][4][4];
#pragma unroll
    for (int mt = 0; mt < 4; mt++)
#pragma unroll
        for (int nt = 0; nt < 4; nt++)
#pragma unroll
            for (int e = 0; e < 4; e++) acc[mt][nt][e] = 0.f;

    const int lr = tid >> 2;
    const int lj = tid & 3;

    for (int kc = 0; kc < 96; kc++) {
        const int k0 = kc * 32;
        const int colA = (k0 < 1024) ? k0 : k0 - 1024;
        const int colB = (k0 < 2048) ? k0 : k0 - 2048;
#pragma unroll
        for (int q = 0; q < 2; q++) {
            const int r = lr + q * 64;
            *(uint4*)&As[r * SPAD + lj * 8] =
                *(const uint4*)&g_outer[(pair0 + r) * 2048 + colA + lj * 8];
            *(uint4*)&Bs[r * SPAD + lj * 8] =
                *(const uint4*)&g_wo[(size_t)r * 2048 + colB + lj * 8];
        }
        __syncthreads();

#pragma unroll
        for (int ks = 0; ks < 2; ks++) {
            const int kb = ks * 16;
            uint32_t a[4][4];
#pragma unroll
            for (int mt = 0; mt < 4; mt++) {
                const int row = warpM * 64 + mt * 16 + (lane & 15);
                const uint32_t addr =
                    asb + (uint32_t)((row * SPAD + kb + (lane >> 4) * 8) * 2);
                ldmat_x4(a[mt], addr);
            }
#pragma unroll
            for (int nt = 0; nt < 4; nt++) {
                const int n = warpN * 32 + nt * 8 + (lane >> 2);
                const int cb = kb + (lane & 3) * 2;
                const uint32_t b0 = *(const uint32_t*)&Bs[n * SPAD + cb];
                const uint32_t b1 = *(const uint32_t*)&Bs[n * SPAD + cb + 8];
#pragma unroll
                for (int mt = 0; mt < 4; mt++)
                    mma16816(acc[mt][nt], a[mt], b0, b1);
            }
        }
        __syncthreads();
    }

    // Epilogue: (acc + bo[p]) / (count[pair] + eps)
#pragma unroll
    for (int mt = 0; mt < 4; mt++) {
#pragma unroll
        for (int h = 0; h < 2; h++) {
            const int rA = warpM * 64 + mt * 16 + (lane >> 2) + h * 8;
            const size_t pair = pair0 + rA;
            const float inv = 1.0f / (g_count[pair] + EPSV);
#pragma unroll
            for (int nt = 0; nt < 4; nt++) {
                const int p = warpN * 32 + nt * 8 + (lane & 3) * 2;
                float2 o;
                o.x = (acc[mt][nt][h * 2 + 0] + bo[p])     * inv;
                o.y = (acc[mt][nt][h * 2 + 1] + bo[p + 1]) * inv;
                *(float2*)&out[pair * DP + p] = o;
            }
        }
    }
}

// ---------------------------------------------------------------------------
extern "C" void kernel_launch(void* const* d_in, const int* in_sizes, int n_in,
                              void* d_out, int out_size)
{
    const float* x    = (const float*)d_in[0];
    const int*   mk   = (const int*)d_in[1];
    const float* ln_g = (const float*)d_in[2];
    const float* ln_b = (const float*)d_in[3];
    const float* wl   = (const float*)d_in[4];
    const float* bl   = (const float*)d_in[5];
    const float* wr   = (const float*)d_in[6];
    const float* br   = (const float*)d_in[7];
    const float* wo   = (const float*)d_in[8];
    const float* bo   = (const float*)d_in[9];
    float* out        = (float*)d_out;

    ln_proj_kernel<<<SEQ * 32, 64>>>(x, mk, ln_g, ln_b, wl, bl, wr, br);
    count_kernel<<<SEQ, 128>>>(mk);
    wo_prep_kernel<<<DP, 256>>>(wo);
    gemm1_kernel<<<dim3(AROWS / 128, AROWS / 128), 256>>>();
    gemm2_kernel<<<PAIRS / 128, 256>>>(bo, out);
}

// round 9
// speedup vs baseline: 4.1733x; 1.2600x over previous
#include <cuda_runtime.h>
#include <cuda_bf16.h>
#include <cstdint>

#define MSA 256
#define SEQ 384
#define DM  256
#define DH  32
#define DP  128
#define EPSV 1e-5f

#define AROWS 12288          // SEQ*DH rows for GEMM1 operands
#define PAIRS (SEQ*SEQ)      // 147456

#define SPAD 40              // smem row pitch in bf16 (32 data + 8 pad)
#define EP   136             // epilogue staging pitch in bf16
#define NK1  24              // gemm1 K' chunks (768/32)
#define NK2  96              // gemm2 K' chunks (3072/32)

// ---------------- scratch (device globals; no allocations allowed) ----------
__device__ __nv_bfloat16 g_l[AROWS * 512];
__device__ __nv_bfloat16 g_r[AROWS * 512];
__device__ __nv_bfloat16 g_outer[(size_t)PAIRS * 2048];
__device__ __nv_bfloat16 g_wo[DP * 2048];
__device__ float g_count[SEQ * SEQ];

// ---------------- helpers ---------------------------------------------------
__device__ __forceinline__ uint32_t smem_u32(const void* p) {
    uint32_t a;
    asm("{ .reg .u64 t; cvta.to.shared.u64 t, %1; cvt.u32.u64 %0, t; }"
        : "=r"(a) : "l"(p));
    return a;
}
__device__ __forceinline__ uint32_t pack_bf16(__nv_bfloat16 a, __nv_bfloat16 b) {
    return (uint32_t)__bfloat16_as_ushort(a) | ((uint32_t)__bfloat16_as_ushort(b) << 16);
}
__device__ __forceinline__ void ldmat_x4(uint32_t* r, uint32_t addr) {
    asm volatile("ldmatrix.sync.aligned.m8n8.x4.shared.b16 {%0,%1,%2,%3}, [%4];"
                 : "=r"(r[0]), "=r"(r[1]), "=r"(r[2]), "=r"(r[3]) : "r"(addr));
}
__device__ __forceinline__ void mma16816(float* c, const uint32_t* a,
                                         uint32_t b0, uint32_t b1) {
    asm volatile(
        "mma.sync.aligned.m16n8k16.row.col.f32.bf16.bf16.f32 "
        "{%0,%1,%2,%3}, {%4,%5,%6,%7}, {%8,%9}, {%0,%1,%2,%3};"
        : "+f"(c[0]), "+f"(c[1]), "+f"(c[2]), "+f"(c[3])
        : "r"(a[0]), "r"(a[1]), "r"(a[2]), "r"(a[3]), "r"(b0), "r"(b1));
}
__device__ __forceinline__ void cp16(uint32_t dst, const void* src) {
    asm volatile("cp.async.ca.shared.global [%0], [%1], 16;" :: "r"(dst), "l"(src));
}
__device__ __forceinline__ void cp_commit() {
    asm volatile("cp.async.commit_group;" ::: "memory");
}
__device__ __forceinline__ void cp_wait1() {
    asm volatile("cp.async.wait_group 1;" ::: "memory");
}
__device__ __forceinline__ void cp_wait0() {
    asm volatile("cp.async.wait_group 0;" ::: "memory");
}

// ---------------------------------------------------------------------------
// Kernel 1: LayerNorm + projections; writes L'/R' as bf16 hi/lo split in
// GEMM1 operand layout (row = i*32+c, col = m (hi) / 256+m (lo)).
// Block = 64 threads: one i, 8 consecutive m. mask is int32.
// ---------------------------------------------------------------------------
__global__ void ln_proj_kernel(const float* __restrict__ x,
                               const int* __restrict__ mask,
                               const float* __restrict__ ln_g,
                               const float* __restrict__ ln_b,
                               const float* __restrict__ wl,
                               const float* __restrict__ bl,
                               const float* __restrict__ wr,
                               const float* __restrict__ br)
{
    __shared__ float xns[8][DM];

    const int t = threadIdx.x;
    const int r = t >> 3;
    const int lane8 = t & 7;
    const int i  = blockIdx.x >> 5;
    const int m0 = (blockIdx.x & 31) * 8;
    const size_t rowg = (size_t)(m0 + r) * SEQ + i;

    const float4* xrow = (const float4*)(x + rowg * DM);

    float4 v[8];
    float s = 0.f, ss = 0.f;
#pragma unroll
    for (int kk = 0; kk < 8; kk++) {
        v[kk] = xrow[kk * 8 + lane8];
        s  += v[kk].x + v[kk].y + v[kk].z + v[kk].w;
        ss += v[kk].x * v[kk].x + v[kk].y * v[kk].y
            + v[kk].z * v[kk].z + v[kk].w * v[kk].w;
    }
#pragma unroll
    for (int off = 4; off >= 1; off >>= 1) {
        s  += __shfl_xor_sync(0xffffffffu, s,  off);
        ss += __shfl_xor_sync(0xffffffffu, ss, off);
    }
    const float mu   = s * (1.0f / DM);
    const float var  = ss * (1.0f / DM) - mu * mu;
    const float rstd = rsqrtf(var + EPSV);

    const float4* g4 = (const float4*)ln_g;
    const float4* b4 = (const float4*)ln_b;
#pragma unroll
    for (int kk = 0; kk < 8; kk++) {
        float4 gg = g4[kk * 8 + lane8];
        float4 bb = b4[kk * 8 + lane8];
        float4 o;
        o.x = (v[kk].x - mu) * rstd * gg.x + bb.x;
        o.y = (v[kk].y - mu) * rstd * gg.y + bb.y;
        o.z = (v[kk].z - mu) * rstd * gg.z + bb.z;
        o.w = (v[kk].w - mu) * rstd * gg.w + bb.w;
        ((float4*)&xns[r][0])[kk * 8 + lane8] = o;
    }
    __syncthreads();

    const float* W  = (t < DH) ? wl : wr;
    const float* Bv = (t < DH) ? bl : br;
    const int c = t & 31;

    float acc[8];
#pragma unroll
    for (int rr = 0; rr < 8; rr++) acc[rr] = 0.f;

    for (int kc = 0; kc < DM; kc += 16) {
        float wreg[16];
#pragma unroll
        for (int kk = 0; kk < 16; kk++)
            wreg[kk] = W[(kc + kk) * DH + c];
#pragma unroll
        for (int rr = 0; rr < 8; rr++) {
            float a = acc[rr];
#pragma unroll
            for (int kk = 0; kk < 16; kk++)
                a += xns[rr][kc + kk] * wreg[kk];
            acc[rr] = a;
        }
    }

    const float bias = Bv[c];
    uint32_t hw[4], lw[4];
#pragma unroll
    for (int q = 0; q < 4; q++) {
        float vs[2];
#pragma unroll
        for (int h = 0; h < 2; h++) {
            const int rr = q * 2 + h;
            const float mf = (mask[(m0 + rr) * SEQ + i] != 0) ? 1.0f : 0.0f;
            vs[h] = (acc[rr] + bias) * mf;
        }
        __nv_bfloat16 h0 = __float2bfloat16(vs[0]);
        __nv_bfloat16 h1 = __float2bfloat16(vs[1]);
        __nv_bfloat16 l0 = __float2bfloat16(vs[0] - __bfloat162float(h0));
        __nv_bfloat16 l1 = __float2bfloat16(vs[1] - __bfloat162float(h1));
        hw[q] = pack_bf16(h0, h1);
        lw[q] = pack_bf16(l0, l1);
    }
    __nv_bfloat16* dst = ((t < DH) ? g_l : g_r) + ((size_t)(i * 32 + c)) * 512;
    *(uint4*)(dst + m0)       = make_uint4(hw[0], hw[1], hw[2], hw[3]);
    *(uint4*)(dst + 256 + m0) = make_uint4(lw[0], lw[1], lw[2], lw[3]);
}

// ---------------------------------------------------------------------------
// Kernel 2: pairwise mask count (int32 mask)
// ---------------------------------------------------------------------------
__global__ void count_kernel(const int* __restrict__ mask)
{
    const int i = blockIdx.x;
    const int j0 = threadIdx.x;
    float acc0 = 0.f, acc1 = 0.f, acc2 = 0.f;
    for (int m = 0; m < MSA; m++) {
        const int* mrow = mask + m * SEQ;
        const float mi = (mrow[i] != 0) ? 1.0f : 0.0f;
        acc0 += mi * ((mrow[j0]       != 0) ? 1.0f : 0.0f);
        acc1 += mi * ((mrow[j0 + 128] != 0) ? 1.0f : 0.0f);
        acc2 += mi * ((mrow[j0 + 256] != 0) ? 1.0f : 0.0f);
    }
    g_count[i * SEQ + j0]       = acc0;
    g_count[i * SEQ + j0 + 128] = acc1;
    g_count[i * SEQ + j0 + 256] = acc2;
}

// ---------------------------------------------------------------------------
// Kernel 3: transpose+split wo -> g_wo[p][cd hi | cd lo]
// ---------------------------------------------------------------------------
__global__ void wo_prep_kernel(const float* __restrict__ wo)
{
    const int p = blockIdx.x;
    for (int k = threadIdx.x; k < 1024; k += 256) {
        float v = wo[(size_t)k * DP + p];
        __nv_bfloat16 h = __float2bfloat16(v);
        __nv_bfloat16 l = __float2bfloat16(v - __bfloat162float(h));
        g_wo[(size_t)p * 2048 + k]        = h;
        g_wo[(size_t)p * 2048 + 1024 + k] = l;
    }
}

// ---------------------------------------------------------------------------
// GEMM1 (mma.sync bf16, cp.async double-buffered): outer = L' x R'^T.
// M=N=12288, K'=768 (hh|hl|lh). CTA 128x128, 8 warps, warp 64x32.
// Epilogue staged through smem for contiguous 1KB-per-pair writes.
// ---------------------------------------------------------------------------
struct G1Smem {
    union {
        __nv_bfloat16 buf[2][2][128 * SPAD];   // [stage][A|B]
        __nv_bfloat16 ep[128 * EP];
    };
};

__global__ void __launch_bounds__(256, 2)
gemm1_kernel()
{
    __shared__ G1Smem sm;

    const int tid  = threadIdx.x;
    const int wid  = tid >> 5;
    const int lane = tid & 31;
    const int warpM = wid & 1;
    const int warpN = wid >> 1;
    const int aRow0 = blockIdx.x * 128;
    const int bRow0 = blockIdx.y * 128;
    const int lr = tid >> 2;
    const int lj = tid & 3;

    float acc[4][4][4];
#pragma unroll
    for (int mt = 0; mt < 4; mt++)
#pragma unroll
        for (int nt = 0; nt < 4; nt++)
#pragma unroll
            for (int e = 0; e < 4; e++) acc[mt][nt][e] = 0.f;

    // ---- async load of one K-chunk into stage kc&1 ----
    auto issue = [&](int kc) {
        const int s  = kc & 1;
        const int k0 = kc * 32;
        const int colA = (k0 < 256) ? k0 : k0 - 256;
        const int colB = (k0 < 512) ? k0 : k0 - 512;
        const uint32_t sa = smem_u32(&sm.buf[s][0][0]);
        const uint32_t sb = smem_u32(&sm.buf[s][1][0]);
#pragma unroll
        for (int q = 0; q < 2; q++) {
            const int r = lr + q * 64;
            cp16(sa + (uint32_t)((r * SPAD + lj * 8) * 2),
                 &g_l[(size_t)(aRow0 + r) * 512 + colA + lj * 8]);
            cp16(sb + (uint32_t)((r * SPAD + lj * 8) * 2),
                 &g_r[(size_t)(bRow0 + r) * 512 + colB + lj * 8]);
        }
        cp_commit();
    };

    issue(0);
    for (int kc = 0; kc < NK1; kc++) {
        if (kc + 1 < NK1) { issue(kc + 1); cp_wait1(); }
        else              { cp_wait0(); }
        __syncthreads();
        const int s = kc & 1;
        const uint32_t sa = smem_u32(&sm.buf[s][0][0]);
        const uint32_t sb = smem_u32(&sm.buf[s][1][0]);
#pragma unroll
        for (int ks = 0; ks < 2; ks++) {
            const int kb = ks * 16;
            uint32_t a[4][4];
#pragma unroll
            for (int mt = 0; mt < 4; mt++) {
                const int row = warpM * 64 + mt * 16 + (lane & 15);
                ldmat_x4(a[mt], sa + (uint32_t)((row * SPAD + kb + (lane >> 4) * 8) * 2));
            }
            uint32_t bf[2][4];
#pragma unroll
            for (int g = 0; g < 2; g++) {
                const int row = warpN * 32 + g * 16 + (lane & 7) + ((lane >> 4) << 3);
                const int col = kb + (((lane >> 3) & 1) << 3);
                ldmat_x4(bf[g], sb + (uint32_t)((row * SPAD + col) * 2));
            }
#pragma unroll
            for (int nt = 0; nt < 4; nt++) {
                const uint32_t b0 = bf[nt >> 1][(nt & 1) * 2];
                const uint32_t b1 = bf[nt >> 1][(nt & 1) * 2 + 1];
#pragma unroll
                for (int mt = 0; mt < 4; mt++)
                    mma16816(acc[mt][nt], a[mt], b0, b1);
            }
        }
        __syncthreads();
    }

    // ---- staged epilogue: two passes (hi, lo) through smem ----
    const int i0 = blockIdx.x * 4;
    const int j0 = blockIdx.y * 4;
#pragma unroll
    for (int half = 0; half < 2; half++) {
        __syncthreads();
#pragma unroll
        for (int mt = 0; mt < 4; mt++)
#pragma unroll
            for (int nt = 0; nt < 4; nt++)
#pragma unroll
                for (int h = 0; h < 2; h++) {
                    const int row  = warpM * 64 + mt * 16 + (lane >> 2) + h * 8;
                    const int colp = warpN * 32 + nt * 8 + (lane & 3) * 2;
                    const float v0 = acc[mt][nt][h * 2 + 0];
                    const float v1 = acc[mt][nt][h * 2 + 1];
                    __nv_bfloat16 x0, x1;
                    if (half == 0) {
                        x0 = __float2bfloat16(v0);
                        x1 = __float2bfloat16(v1);
                    } else {
                        __nv_bfloat16 h0 = __float2bfloat16(v0);
                        __nv_bfloat16 h1 = __float2bfloat16(v1);
                        x0 = __float2bfloat16(v0 - __bfloat162float(h0));
                        x1 = __float2bfloat16(v1 - __bfloat162float(h1));
                    }
                    *(uint32_t*)&sm.ep[row * EP + colp] = pack_bf16(x0, x1);
                }
        __syncthreads();
#pragma unroll
        for (int pp = 0; pp < 2; pp++) {
            const int pr = wid * 2 + pp;
            const int ii = pr >> 2, jj = pr & 3;
            const size_t pair = (size_t)(i0 + ii) * SEQ + (j0 + jj);
#pragma unroll
            for (int it = 0; it < 4; it++) {
                const int t = it * 32 + lane;
                const int c = t >> 2, d8 = (t & 3) * 8;
                uint4 v = *(const uint4*)&sm.ep[(ii * 32 + c) * EP + jj * 32 + d8];
                *(uint4*)&g_outer[pair * 2048 + half * 1024 + c * 32 + d8] = v;
            }
        }
    }
}

// ---------------------------------------------------------------------------
// GEMM2 (mma.sync bf16, cp.async double-buffered): out = outer x wo^T.
// M=147456 (pairs), N=128 (p), K'=3072. Epilogue: +bo, /(count+eps).
// ---------------------------------------------------------------------------
__global__ void __launch_bounds__(256, 2)
gemm2_kernel(const float* __restrict__ bo, float* __restrict__ out)
{
    __shared__ __nv_bfloat16 Abuf[2][128 * SPAD];
    __shared__ __nv_bfloat16 Bbuf[2][128 * SPAD];

    const int tid  = threadIdx.x;
    const int wid  = tid >> 5;
    const int lane = tid & 31;
    const int warpM = wid & 1;
    const int warpN = wid >> 1;
    const size_t pair0 = (size_t)blockIdx.x * 128;
    const int lr = tid >> 2;
    const int lj = tid & 3;

    float acc[4][4][4];
#pragma unroll
    for (int mt = 0; mt < 4; mt++)
#pragma unroll
        for (int nt = 0; nt < 4; nt++)
#pragma unroll
            for (int e = 0; e < 4; e++) acc[mt][nt][e] = 0.f;

    auto issue = [&](int kc) {
        const int s  = kc & 1;
        const int k0 = kc * 32;
        const int colA = (k0 < 1024) ? k0 : k0 - 1024;
        const int colB = (k0 < 2048) ? k0 : k0 - 2048;
        const uint32_t sa = smem_u32(&Abuf[s][0]);
        const uint32_t sb = smem_u32(&Bbuf[s][0]);
#pragma unroll
        for (int q = 0; q < 2; q++) {
            const int r = lr + q * 64;
            cp16(sa + (uint32_t)((r * SPAD + lj * 8) * 2),
                 &g_outer[(pair0 + r) * 2048 + colA + lj * 8]);
            cp16(sb + (uint32_t)((r * SPAD + lj * 8) * 2),
                 &g_wo[(size_t)r * 2048 + colB + lj * 8]);
        }
        cp_commit();
    };

    issue(0);
    for (int kc = 0; kc < NK2; kc++) {
        if (kc + 1 < NK2) { issue(kc + 1); cp_wait1(); }
        else              { cp_wait0(); }
        __syncthreads();
        const int s = kc & 1;
        const uint32_t sa = smem_u32(&Abuf[s][0]);
        const uint32_t sb = smem_u32(&Bbuf[s][0]);
#pragma unroll
        for (int ks = 0; ks < 2; ks++) {
            const int kb = ks * 16;
            uint32_t a[4][4];
#pragma unroll
            for (int mt = 0; mt < 4; mt++) {
                const int row = warpM * 64 + mt * 16 + (lane & 15);
                ldmat_x4(a[mt], sa + (uint32_t)((row * SPAD + kb + (lane >> 4) * 8) * 2));
            }
            uint32_t bf[2][4];
#pragma unroll
            for (int g = 0; g < 2; g++) {
                const int row = warpN * 32 + g * 16 + (lane & 7) + ((lane >> 4) << 3);
                const int col = kb + (((lane >> 3) & 1) << 3);
                ldmat_x4(bf[g], sb + (uint32_t)((row * SPAD + col) * 2));
            }
#pragma unroll
            for (int nt = 0; nt < 4; nt++) {
                const uint32_t b0 = bf[nt >> 1][(nt & 1) * 2];
                const uint32_t b1 = bf[nt >> 1][(nt & 1) * 2 + 1];
#pragma unroll
                for (int mt = 0; mt < 4; mt++)
                    mma16816(acc[mt][nt], a[mt], b0, b1);
            }
        }
        __syncthreads();
    }

    // Epilogue: (acc + bo[p]) / (count[pair] + eps)
#pragma unroll
    for (int mt = 0; mt < 4; mt++) {
#pragma unroll
        for (int h = 0; h < 2; h++) {
            const int rA = warpM * 64 + mt * 16 + (lane >> 2) + h * 8;
            const size_t pair = pair0 + rA;
            const float inv = 1.0f / (g_count[pair] + EPSV);
#pragma unroll
            for (int nt = 0; nt < 4; nt++) {
                const int p = warpN * 32 + nt * 8 + (lane & 3) * 2;
                float2 o;
                o.x = (acc[mt][nt][h * 2 + 0] + bo[p])     * inv;
                o.y = (acc[mt][nt][h * 2 + 1] + bo[p + 1]) * inv;
                *(float2*)&out[pair * DP + p] = o;
            }
        }
    }
}

// ---------------------------------------------------------------------------
extern "C" void kernel_launch(void* const* d_in, const int* in_sizes, int n_in,
                              void* d_out, int out_size)
{
    const float* x    = (const float*)d_in[0];
    const int*   mk   = (const int*)d_in[1];
    const float* ln_g = (const float*)d_in[2];
    const float* ln_b = (const float*)d_in[3];
    const float* wl   = (const float*)d_in[4];
    const float* bl   = (const float*)d_in[5];
    const float* wr   = (const float*)d_in[6];
    const float* br   = (const float*)d_in[7];
    const float* wo   = (const float*)d_in[8];
    const float* bo   = (const float*)d_in[9];
    float* out        = (float*)d_out;

    ln_proj_kernel<<<SEQ * 32, 64>>>(x, mk, ln_g, ln_b, wl, bl, wr, br);
    count_kernel<<<SEQ, 128>>>(mk);
    wo_prep_kernel<<<DP, 256>>>(wo);
    gemm1_kernel<<<dim3(AROWS / 128, AROWS / 128), 256>>>();
    gemm2_kernel<<<PAIRS / 128, 256>>>(bo, out);
}

// round 12
// speedup vs baseline: 4.8636x; 1.1654x over previous
#include <cuda_runtime.h>
#include <cuda_bf16.h>
#include <cstdint>

#define MSA 256
#define SEQ 384
#define DM  256
#define DH  32
#define DP  128
#define EPSV 1e-5f

#define AROWS 12288          // SEQ*DH rows for GEMM1 operands
#define PAIRS (SEQ*SEQ)      // 147456

#define SPAD 40              // smem row pitch in bf16 (32 data + 8 pad)
#define EP   136             // epilogue staging pitch in bf16
#define NK1  24              // gemm1 K' chunks (768/32)
#define NK2  96              // gemm2 K' chunks (3072/32)

// ---------------- scratch (device globals; no allocations allowed) ----------
__device__ __nv_bfloat16 g_l[AROWS * 512];
__device__ __nv_bfloat16 g_r[AROWS * 512];
__device__ __nv_bfloat16 g_outer[(size_t)PAIRS * 2048];
__device__ __nv_bfloat16 g_wo[DP * 2048];
__device__ float g_count[SEQ * SEQ];

// ---------------- helpers ---------------------------------------------------
__device__ __forceinline__ uint32_t smem_u32(const void* p) {
    uint32_t a;
    asm("{ .reg .u64 t; cvta.to.shared.u64 t, %1; cvt.u32.u64 %0, t; }"
        : "=r"(a) : "l"(p));
    return a;
}
__device__ __forceinline__ uint32_t pack_bf16(__nv_bfloat16 a, __nv_bfloat16 b) {
    return (uint32_t)__bfloat16_as_ushort(a) | ((uint32_t)__bfloat16_as_ushort(b) << 16);
}
__device__ __forceinline__ void ldmat_x4(uint32_t* r, uint32_t addr) {
    asm volatile("ldmatrix.sync.aligned.m8n8.x4.shared.b16 {%0,%1,%2,%3}, [%4];"
                 : "=r"(r[0]), "=r"(r[1]), "=r"(r[2]), "=r"(r[3]) : "r"(addr));
}
__device__ __forceinline__ void mma16816(float* c, const uint32_t* a,
                                         uint32_t b0, uint32_t b1) {
    asm volatile(
        "mma.sync.aligned.m16n8k16.row.col.f32.bf16.bf16.f32 "
        "{%0,%1,%2,%3}, {%4,%5,%6,%7}, {%8,%9}, {%0,%1,%2,%3};"
        : "+f"(c[0]), "+f"(c[1]), "+f"(c[2]), "+f"(c[3])
        : "r"(a[0]), "r"(a[1]), "r"(a[2]), "r"(a[3]), "r"(b0), "r"(b1));
}
__device__ __forceinline__ void cp16(uint32_t dst, const void* src) {
    asm volatile("cp.async.ca.shared.global [%0], [%1], 16;" :: "r"(dst), "l"(src));
}
__device__ __forceinline__ void cp_commit() {
    asm volatile("cp.async.commit_group;" ::: "memory");
}
__device__ __forceinline__ void cp_wait1() {
    asm volatile("cp.async.wait_group 1;" ::: "memory");
}
__device__ __forceinline__ void cp_wait0() {
    asm volatile("cp.async.wait_group 0;" ::: "memory");
}

// ---------------------------------------------------------------------------
// Kernel 1: LayerNorm + projections; writes L'/R' as bf16 hi/lo split in
// GEMM1 operand layout (row = i*32+c, col = m (hi) / 256+m (lo)).
// Block = 64 threads: one i, 32 consecutive m (4x W reuse vs 8-row version).
// mask is int32.
// ---------------------------------------------------------------------------
__global__ void ln_proj_kernel(const float* __restrict__ x,
                               const int* __restrict__ mask,
                               const float* __restrict__ ln_g,
                               const float* __restrict__ ln_b,
                               const float* __restrict__ wl,
                               const float* __restrict__ bl,
                               const float* __restrict__ wr,
                               const float* __restrict__ br)
{
    __shared__ float xns[32][DM];

    const int t = threadIdx.x;          // 0..63
    const int r = t >> 3;               // 0..7
    const int lane8 = t & 7;
    const int i  = blockIdx.x >> 3;
    const int m0 = (blockIdx.x & 7) * 32;

    const float4* g4 = (const float4*)ln_g;
    const float4* b4 = (const float4*)ln_b;

    // ---- Phase A: LN for 32 rows (4 passes of 8 rows) ----
#pragma unroll
    for (int it = 0; it < 4; it++) {
        const int rr = it * 8 + r;
        const size_t rowg = (size_t)(m0 + rr) * SEQ + i;
        const float4* xrow = (const float4*)(x + rowg * DM);

        float4 v[8];
        float s = 0.f, ss = 0.f;
#pragma unroll
        for (int kk = 0; kk < 8; kk++) {
            v[kk] = xrow[kk * 8 + lane8];
            s  += v[kk].x + v[kk].y + v[kk].z + v[kk].w;
            ss += v[kk].x * v[kk].x + v[kk].y * v[kk].y
                + v[kk].z * v[kk].z + v[kk].w * v[kk].w;
        }
#pragma unroll
        for (int off = 4; off >= 1; off >>= 1) {
            s  += __shfl_xor_sync(0xffffffffu, s,  off);
            ss += __shfl_xor_sync(0xffffffffu, ss, off);
        }
        const float mu   = s * (1.0f / DM);
        const float var  = ss * (1.0f / DM) - mu * mu;
        const float rstd = rsqrtf(var + EPSV);

#pragma unroll
        for (int kk = 0; kk < 8; kk++) {
            float4 gg = g4[kk * 8 + lane8];
            float4 bb = b4[kk * 8 + lane8];
            float4 o;
            o.x = (v[kk].x - mu) * rstd * gg.x + bb.x;
            o.y = (v[kk].y - mu) * rstd * gg.y + bb.y;
            o.z = (v[kk].z - mu) * rstd * gg.z + bb.z;
            o.w = (v[kk].w - mu) * rstd * gg.w + bb.w;
            ((float4*)&xns[rr][0])[kk * 8 + lane8] = o;
        }
    }
    __syncthreads();

    // ---- Phase B: projections, 32 rows per column-owner thread ----
    const float* W  = (t < DH) ? wl : wr;
    const float* Bv = (t < DH) ? bl : br;
    const int c = t & 31;

    float acc[32];
#pragma unroll
    for (int rr = 0; rr < 32; rr++) acc[rr] = 0.f;

    for (int kc = 0; kc < DM; kc += 8) {
        float wreg[8];
#pragma unroll
        for (int kk = 0; kk < 8; kk++)
            wreg[kk] = W[(kc + kk) * DH + c];
#pragma unroll
        for (int rr = 0; rr < 32; rr++) {
            float a = acc[rr];
#pragma unroll
            for (int kk = 0; kk < 8; kk++)
                a += xns[rr][kc + kk] * wreg[kk];
            acc[rr] = a;
        }
    }

    const float bias = Bv[c];
#pragma unroll
    for (int rr = 0; rr < 32; rr++) {
        const float mf = (mask[(m0 + rr) * SEQ + i] != 0) ? 1.0f : 0.0f;
        acc[rr] = (acc[rr] + bias) * mf;
    }

    __nv_bfloat16* dst = ((t < DH) ? g_l : g_r) + ((size_t)(i * 32 + c)) * 512;
#pragma unroll
    for (int q = 0; q < 4; q++) {
        uint32_t hw[4], lw[4];
#pragma unroll
        for (int u = 0; u < 4; u++) {
            const float v0 = acc[q * 8 + u * 2];
            const float v1 = acc[q * 8 + u * 2 + 1];
            __nv_bfloat16 h0 = __float2bfloat16(v0);
            __nv_bfloat16 h1 = __float2bfloat16(v1);
            __nv_bfloat16 l0 = __float2bfloat16(v0 - __bfloat162float(h0));
            __nv_bfloat16 l1 = __float2bfloat16(v1 - __bfloat162float(h1));
            hw[u] = pack_bf16(h0, h1);
            lw[u] = pack_bf16(l0, l1);
        }
        *(uint4*)(dst + m0 + q * 8)       = make_uint4(hw[0], hw[1], hw[2], hw[3]);
        *(uint4*)(dst + 256 + m0 + q * 8) = make_uint4(lw[0], lw[1], lw[2], lw[3]);
    }
}

// ---------------------------------------------------------------------------
// Kernel 2: pairwise mask count (int32 mask)
// ---------------------------------------------------------------------------
__global__ void count_kernel(const int* __restrict__ mask)
{
    const int i = blockIdx.x;
    const int j0 = threadIdx.x;
    float acc0 = 0.f, acc1 = 0.f, acc2 = 0.f;
    for (int m = 0; m < MSA; m++) {
        const int* mrow = mask + m * SEQ;
        const float mi = (mrow[i] != 0) ? 1.0f : 0.0f;
        acc0 += mi * ((mrow[j0]       != 0) ? 1.0f : 0.0f);
        acc1 += mi * ((mrow[j0 + 128] != 0) ? 1.0f : 0.0f);
        acc2 += mi * ((mrow[j0 + 256] != 0) ? 1.0f : 0.0f);
    }
    g_count[i * SEQ + j0]       = acc0;
    g_count[i * SEQ + j0 + 128] = acc1;
    g_count[i * SEQ + j0 + 256] = acc2;
}

// ---------------------------------------------------------------------------
// Kernel 3: transpose+split wo -> g_wo[p][cd hi | cd lo]
// ---------------------------------------------------------------------------
__global__ void wo_prep_kernel(const float* __restrict__ wo)
{
    const int p = blockIdx.x;
    for (int k = threadIdx.x; k < 1024; k += 256) {
        float v = wo[(size_t)k * DP + p];
        __nv_bfloat16 h = __float2bfloat16(v);
        __nv_bfloat16 l = __float2bfloat16(v - __bfloat162float(h));
        g_wo[(size_t)p * 2048 + k]        = h;
        g_wo[(size_t)p * 2048 + 1024 + k] = l;
    }
}

// ---------------------------------------------------------------------------
// GEMM1 (mma.sync bf16, cp.async double-buffered): outer = L' x R'^T.
// M=N=12288, K'=768 (hh|hl|lh). CTA 128x128, 4 warps (2x2), warp 64x64.
// Per K16 step: 8 LDSM feed 32 HMMA. Epilogue staged via smem.
// ---------------------------------------------------------------------------
struct G1Smem {
    union {
        __nv_bfloat16 buf[2][2][128 * SPAD];   // [stage][A|B]
        __nv_bfloat16 ep[128 * EP];
    };
};

__global__ void __launch_bounds__(128, 2)
gemm1_kernel()
{
    __shared__ G1Smem sm;

    const int tid  = threadIdx.x;
    const int wid  = tid >> 5;
    const int lane = tid & 31;
    const int warpM = wid & 1;
    const int warpN = wid >> 1;
    const int aRow0 = blockIdx.x * 128;
    const int bRow0 = blockIdx.y * 128;
    const int lr = tid >> 2;            // 0..31
    const int lj = tid & 3;

    float acc[4][8][4];
#pragma unroll
    for (int mt = 0; mt < 4; mt++)
#pragma unroll
        for (int nt = 0; nt < 8; nt++)
#pragma unroll
            for (int e = 0; e < 4; e++) acc[mt][nt][e] = 0.f;

    auto issue = [&](int kc) {
        const int s  = kc & 1;
        const int k0 = kc * 32;
        const int colA = (k0 < 256) ? k0 : k0 - 256;
        const int colB = (k0 < 512) ? k0 : k0 - 512;
        const uint32_t sa = smem_u32(&sm.buf[s][0][0]);
        const uint32_t sb = smem_u32(&sm.buf[s][1][0]);
#pragma unroll
        for (int q = 0; q < 4; q++) {
            const int r = lr + q * 32;
            cp16(sa + (uint32_t)((r * SPAD + lj * 8) * 2),
                 &g_l[(size_t)(aRow0 + r) * 512 + colA + lj * 8]);
            cp16(sb + (uint32_t)((r * SPAD + lj * 8) * 2),
                 &g_r[(size_t)(bRow0 + r) * 512 + colB + lj * 8]);
        }
        cp_commit();
    };

    issue(0);
    for (int kc = 0; kc < NK1; kc++) {
        if (kc + 1 < NK1) { issue(kc + 1); cp_wait1(); }
        else              { cp_wait0(); }
        __syncthreads();
        const int s = kc & 1;
        const uint32_t sa = smem_u32(&sm.buf[s][0][0]);
        const uint32_t sb = smem_u32(&sm.buf[s][1][0]);
#pragma unroll
        for (int ks = 0; ks < 2; ks++) {
            const int kb = ks * 16;
            uint32_t a[4][4];
#pragma unroll
            for (int mt = 0; mt < 4; mt++) {
                const int row = warpM * 64 + mt * 16 + (lane & 15);
                ldmat_x4(a[mt], sa + (uint32_t)((row * SPAD + kb + (lane >> 4) * 8) * 2));
            }
            uint32_t bf[4][4];
#pragma unroll
            for (int g = 0; g < 4; g++) {
                const int row = warpN * 64 + g * 16 + (lane & 7) + ((lane >> 4) << 3);
                const int col = kb + (((lane >> 3) & 1) << 3);
                ldmat_x4(bf[g], sb + (uint32_t)((row * SPAD + col) * 2));
            }
#pragma unroll
            for (int nt = 0; nt < 8; nt++) {
                const uint32_t b0 = bf[nt >> 1][(nt & 1) * 2];
                const uint32_t b1 = bf[nt >> 1][(nt & 1) * 2 + 1];
#pragma unroll
                for (int mt = 0; mt < 4; mt++)
                    mma16816(acc[mt][nt], a[mt], b0, b1);
            }
        }
        __syncthreads();
    }

    // ---- staged epilogue: two passes (hi, lo) through smem ----
    const int i0 = blockIdx.x * 4;
    const int j0 = blockIdx.y * 4;
#pragma unroll
    for (int half = 0; half < 2; half++) {
        __syncthreads();
#pragma unroll
        for (int mt = 0; mt < 4; mt++)
#pragma unroll
            for (int nt = 0; nt < 8; nt++)
#pragma unroll
                for (int h = 0; h < 2; h++) {
                    const int row  = warpM * 64 + mt * 16 + (lane >> 2) + h * 8;
                    const int colp = warpN * 64 + nt * 8 + (lane & 3) * 2;
                    const float v0 = acc[mt][nt][h * 2 + 0];
                    const float v1 = acc[mt][nt][h * 2 + 1];
                    __nv_bfloat16 x0, x1;
                    if (half == 0) {
                        x0 = __float2bfloat16(v0);
                        x1 = __float2bfloat16(v1);
                    } else {
                        __nv_bfloat16 h0 = __float2bfloat16(v0);
                        __nv_bfloat16 h1 = __float2bfloat16(v1);
                        x0 = __float2bfloat16(v0 - __bfloat162float(h0));
                        x1 = __float2bfloat16(v1 - __bfloat162float(h1));
                    }
                    *(uint32_t*)&sm.ep[row * EP + colp] = pack_bf16(x0, x1);
                }
        __syncthreads();
#pragma unroll
        for (int pp = 0; pp < 4; pp++) {
            const int pr = wid * 4 + pp;
            const int ii = pr >> 2, jj = pr & 3;
            const size_t pair = (size_t)(i0 + ii) * SEQ + (j0 + jj);
#pragma unroll
            for (int it = 0; it < 4; it++) {
                const int t = it * 32 + lane;
                const int c = t >> 2, d8 = (t & 3) * 8;
                uint4 v = *(const uint4*)&sm.ep[(ii * 32 + c) * EP + jj * 32 + d8];
                *(uint4*)&g_outer[pair * 2048 + half * 1024 + c * 32 + d8] = v;
            }
        }
    }
}

// ---------------------------------------------------------------------------
// GEMM2 (mma.sync bf16, cp.async double-buffered): out = outer x wo^T.
// M=147456 (pairs), N=128 (p), K'=3072. 4 warps (2x2), warp 64x64.
// Epilogue: +bo, /(count+eps).
// ---------------------------------------------------------------------------
__global__ void __launch_bounds__(128, 2)
gemm2_kernel(const float* __restrict__ bo, float* __restrict__ out)
{
    __shared__ __nv_bfloat16 Abuf[2][128 * SPAD];
    __shared__ __nv_bfloat16 Bbuf[2][128 * SPAD];

    const int tid  = threadIdx.x;
    const int wid  = tid >> 5;
    const int lane = tid & 31;
    const int warpM = wid & 1;
    const int warpN = wid >> 1;
    const size_t pair0 = (size_t)blockIdx.x * 128;
    const int lr = tid >> 2;
    const int lj = tid & 3;

    float acc[4][8][4];
#pragma unroll
    for (int mt = 0; mt < 4; mt++)
#pragma unroll
        for (int nt = 0; nt < 8; nt++)
#pragma unroll
            for (int e = 0; e < 4; e++) acc[mt][nt][e] = 0.f;

    auto issue = [&](int kc) {
        const int s  = kc & 1;
        const int k0 = kc * 32;
        const int colA = (k0 < 1024) ? k0 : k0 - 1024;
        const int colB = (k0 < 2048) ? k0 : k0 - 2048;
        const uint32_t sa = smem_u32(&Abuf[s][0]);
        const uint32_t sb = smem_u32(&Bbuf[s][0]);
#pragma unroll
        for (int q = 0; q < 4; q++) {
            const int r = lr + q * 32;
            cp16(sa + (uint32_t)((r * SPAD + lj * 8) * 2),
                 &g_outer[(pair0 + r) * 2048 + colA + lj * 8]);
            cp16(sb + (uint32_t)((r * SPAD + lj * 8) * 2),
                 &g_wo[(size_t)r * 2048 + colB + lj * 8]);
        }
        cp_commit();
    };

    issue(0);
    for (int kc = 0; kc < NK2; kc++) {
        if (kc + 1 < NK2) { issue(kc + 1); cp_wait1(); }
        else              { cp_wait0(); }
        __syncthreads();
        const int s = kc & 1;
        const uint32_t sa = smem_u32(&Abuf[s][0]);
        const uint32_t sb = smem_u32(&Bbuf[s][0]);
#pragma unroll
        for (int ks = 0; ks < 2; ks++) {
            const int kb = ks * 16;
            uint32_t a[4][4];
#pragma unroll
            for (int mt = 0; mt < 4; mt++) {
                const int row = warpM * 64 + mt * 16 + (lane & 15);
                ldmat_x4(a[mt], sa + (uint32_t)((row * SPAD + kb + (lane >> 4) * 8) * 2));
            }
            uint32_t bf[4][4];
#pragma unroll
            for (int g = 0; g < 4; g++) {
                const int row = warpN * 64 + g * 16 + (lane & 7) + ((lane >> 4) << 3);
                const int col = kb + (((lane >> 3) & 1) << 3);
                ldmat_x4(bf[g], sb + (uint32_t)((row * SPAD + col) * 2));
            }
#pragma unroll
            for (int nt = 0; nt < 8; nt++) {
                const uint32_t b0 = bf[nt >> 1][(nt & 1) * 2];
                const uint32_t b1 = bf[nt >> 1][(nt & 1) * 2 + 1];
#pragma unroll
                for (int mt = 0; mt < 4; mt++)
                    mma16816(acc[mt][nt], a[mt], b0, b1);
            }
        }
        __syncthreads();
    }

    // Epilogue: (acc + bo[p]) / (count[pair] + eps)
#pragma unroll
    for (int mt = 0; mt < 4; mt++) {
#pragma unroll
        for (int h = 0; h < 2; h++) {
            const int rA = warpM * 64 + mt * 16 + (lane >> 2) + h * 8;
            const size_t pair = pair0 + rA;
            const float inv = 1.0f / (g_count[pair] + EPSV);
#pragma unroll
            for (int nt = 0; nt < 8; nt++) {
                const int p = warpN * 64 + nt * 8 + (lane & 3) * 2;
                float2 o;
                o.x = (acc[mt][nt][h * 2 + 0] + bo[p])     * inv;
                o.y = (acc[mt][nt][h * 2 + 1] + bo[p + 1]) * inv;
                *(float2*)&out[pair * DP + p] = o;
            }
        }
    }
}

// ---------------------------------------------------------------------------
extern "C" void kernel_launch(void* const* d_in, const int* in_sizes, int n_in,
                              void* d_out, int out_size)
{
    const float* x    = (const float*)d_in[0];
    const int*   mk   = (const int*)d_in[1];
    const float* ln_g = (const float*)d_in[2];
    const float* ln_b = (const float*)d_in[3];
    const float* wl   = (const float*)d_in[4];
    const float* bl   = (const float*)d_in[5];
    const float* wr   = (const float*)d_in[6];
    const float* br   = (const float*)d_in[7];
    const float* wo   = (const float*)d_in[8];
    const float* bo   = (const float*)d_in[9];
    float* out        = (float*)d_out;

    ln_proj_kernel<<<SEQ * 8, 64>>>(x, mk, ln_g, ln_b, wl, bl, wr, br);
    count_kernel<<<SEQ, 128>>>(mk);
    wo_prep_kernel<<<DP, 256>>>(wo);
    gemm1_kernel<<<dim3(AROWS / 128, AROWS / 128), 128>>>();
    gemm2_kernel<<<PAIRS / 128, 128>>>(bo, out);
}

// round 13
// speedup vs baseline: 5.0230x; 1.0328x over previous
#include <cuda_runtime.h>
#include <cuda_bf16.h>
#include <cstdint>

#define MSA 256
#define SEQ 384
#define DM  256
#define DH  32
#define DP  128
#define EPSV 1e-5f

#define AROWS 12288          // SEQ*DH rows for GEMM1 operands
#define PAIRS (SEQ*SEQ)      // 147456

#define BK   64              // K-chunk
#define SPAD 72              // smem row pitch in bf16 (64 data + 8 pad)
#define EP   136             // epilogue staging pitch in bf16
#define NK1  12              // gemm1 K' chunks (768/64)
#define NK2  48              // gemm2 K' chunks (3072/64)

#define ABYTES (128 * SPAD * 2)          // one operand, one stage
#define STAGEB (2 * ABYTES)              // A+B one stage
#define SMEMSZ (2 * STAGEB)              // 73728 bytes

// ---------------- scratch (device globals; no allocations allowed) ----------
__device__ __nv_bfloat16 g_l[AROWS * 512];
__device__ __nv_bfloat16 g_r[AROWS * 512];
__device__ __nv_bfloat16 g_outer[(size_t)PAIRS * 2048];
__device__ __nv_bfloat16 g_wo[DP * 2048];
__device__ float g_count[SEQ * SEQ];

// ---------------- helpers ---------------------------------------------------
__device__ __forceinline__ uint32_t smem_u32(const void* p) {
    uint32_t a;
    asm("{ .reg .u64 t; cvta.to.shared.u64 t, %1; cvt.u32.u64 %0, t; }"
        : "=r"(a) : "l"(p));
    return a;
}
__device__ __forceinline__ uint32_t pack_bf16(__nv_bfloat16 a, __nv_bfloat16 b) {
    return (uint32_t)__bfloat16_as_ushort(a) | ((uint32_t)__bfloat16_as_ushort(b) << 16);
}
__device__ __forceinline__ void ldmat_x4(uint32_t* r, uint32_t addr) {
    asm volatile("ldmatrix.sync.aligned.m8n8.x4.shared.b16 {%0,%1,%2,%3}, [%4];"
                 : "=r"(r[0]), "=r"(r[1]), "=r"(r[2]), "=r"(r[3]) : "r"(addr));
}
__device__ __forceinline__ void mma16816(float* c, const uint32_t* a,
                                         uint32_t b0, uint32_t b1) {
    asm volatile(
        "mma.sync.aligned.m16n8k16.row.col.f32.bf16.bf16.f32 "
        "{%0,%1,%2,%3}, {%4,%5,%6,%7}, {%8,%9}, {%0,%1,%2,%3};"
        : "+f"(c[0]), "+f"(c[1]), "+f"(c[2]), "+f"(c[3])
        : "r"(a[0]), "r"(a[1]), "r"(a[2]), "r"(a[3]), "r"(b0), "r"(b1));
}
__device__ __forceinline__ void cp16(uint32_t dst, const void* src) {
    asm volatile("cp.async.ca.shared.global [%0], [%1], 16;" :: "r"(dst), "l"(src));
}
__device__ __forceinline__ void cp_commit() {
    asm volatile("cp.async.commit_group;" ::: "memory");
}
__device__ __forceinline__ void cp_wait1() {
    asm volatile("cp.async.wait_group 1;" ::: "memory");
}
__device__ __forceinline__ void cp_wait0() {
    asm volatile("cp.async.wait_group 0;" ::: "memory");
}

// ---------------------------------------------------------------------------
// Kernel 1: LayerNorm + projections; writes L'/R' as bf16 hi/lo split in
// GEMM1 operand layout (row = i*32+c, col = m (hi) / 256+m (lo)).
// Block = 64 threads: one i, 32 consecutive m. mask is int32.
// ---------------------------------------------------------------------------
__global__ void ln_proj_kernel(const float* __restrict__ x,
                               const int* __restrict__ mask,
                               const float* __restrict__ ln_g,
                               const float* __restrict__ ln_b,
                               const float* __restrict__ wl,
                               const float* __restrict__ bl,
                               const float* __restrict__ wr,
                               const float* __restrict__ br)
{
    __shared__ float xns[32][DM];

    const int t = threadIdx.x;          // 0..63
    const int r = t >> 3;               // 0..7
    const int lane8 = t & 7;
    const int i  = blockIdx.x >> 3;
    const int m0 = (blockIdx.x & 7) * 32;

    const float4* g4 = (const float4*)ln_g;
    const float4* b4 = (const float4*)ln_b;

#pragma unroll
    for (int it = 0; it < 4; it++) {
        const int rr = it * 8 + r;
        const size_t rowg = (size_t)(m0 + rr) * SEQ + i;
        const float4* xrow = (const float4*)(x + rowg * DM);

        float4 v[8];
        float s = 0.f, ss = 0.f;
#pragma unroll
        for (int kk = 0; kk < 8; kk++) {
            v[kk] = xrow[kk * 8 + lane8];
            s  += v[kk].x + v[kk].y + v[kk].z + v[kk].w;
            ss += v[kk].x * v[kk].x + v[kk].y * v[kk].y
                + v[kk].z * v[kk].z + v[kk].w * v[kk].w;
        }
#pragma unroll
        for (int off = 4; off >= 1; off >>= 1) {
            s  += __shfl_xor_sync(0xffffffffu, s,  off);
            ss += __shfl_xor_sync(0xffffffffu, ss, off);
        }
        const float mu   = s * (1.0f / DM);
        const float var  = ss * (1.0f / DM) - mu * mu;
        const float rstd = rsqrtf(var + EPSV);

#pragma unroll
        for (int kk = 0; kk < 8; kk++) {
            float4 gg = g4[kk * 8 + lane8];
            float4 bb = b4[kk * 8 + lane8];
            float4 o;
            o.x = (v[kk].x - mu) * rstd * gg.x + bb.x;
            o.y = (v[kk].y - mu) * rstd * gg.y + bb.y;
            o.z = (v[kk].z - mu) * rstd * gg.z + bb.z;
            o.w = (v[kk].w - mu) * rstd * gg.w + bb.w;
            ((float4*)&xns[rr][0])[kk * 8 + lane8] = o;
        }
    }
    __syncthreads();

    const float* W  = (t < DH) ? wl : wr;
    const float* Bv = (t < DH) ? bl : br;
    const int c = t & 31;

    float acc[32];
#pragma unroll
    for (int rr = 0; rr < 32; rr++) acc[rr] = 0.f;

    for (int kc = 0; kc < DM; kc += 8) {
        float wreg[8];
#pragma unroll
        for (int kk = 0; kk < 8; kk++)
            wreg[kk] = W[(kc + kk) * DH + c];
#pragma unroll
        for (int rr = 0; rr < 32; rr++) {
            float a = acc[rr];
#pragma unroll
            for (int kk = 0; kk < 8; kk++)
                a += xns[rr][kc + kk] * wreg[kk];
            acc[rr] = a;
        }
    }

    const float bias = Bv[c];
#pragma unroll
    for (int rr = 0; rr < 32; rr++) {
        const float mf = (mask[(m0 + rr) * SEQ + i] != 0) ? 1.0f : 0.0f;
        acc[rr] = (acc[rr] + bias) * mf;
    }

    __nv_bfloat16* dst = ((t < DH) ? g_l : g_r) + ((size_t)(i * 32 + c)) * 512;
#pragma unroll
    for (int q = 0; q < 4; q++) {
        uint32_t hw[4], lw[4];
#pragma unroll
        for (int u = 0; u < 4; u++) {
            const float v0 = acc[q * 8 + u * 2];
            const float v1 = acc[q * 8 + u * 2 + 1];
            __nv_bfloat16 h0 = __float2bfloat16(v0);
            __nv_bfloat16 h1 = __float2bfloat16(v1);
            __nv_bfloat16 l0 = __float2bfloat16(v0 - __bfloat162float(h0));
            __nv_bfloat16 l1 = __float2bfloat16(v1 - __bfloat162float(h1));
            hw[u] = pack_bf16(h0, h1);
            lw[u] = pack_bf16(l0, l1);
        }
        *(uint4*)(dst + m0 + q * 8)       = make_uint4(hw[0], hw[1], hw[2], hw[3]);
        *(uint4*)(dst + 256 + m0 + q * 8) = make_uint4(lw[0], lw[1], lw[2], lw[3]);
    }
}

// ---------------------------------------------------------------------------
// Kernel 2: pairwise mask count (int32 mask)
// ---------------------------------------------------------------------------
__global__ void count_kernel(const int* __restrict__ mask)
{
    const int i = blockIdx.x;
    const int j0 = threadIdx.x;
    float acc0 = 0.f, acc1 = 0.f, acc2 = 0.f;
    for (int m = 0; m < MSA; m++) {
        const int* mrow = mask + m * SEQ;
        const float mi = (mrow[i] != 0) ? 1.0f : 0.0f;
        acc0 += mi * ((mrow[j0]       != 0) ? 1.0f : 0.0f);
        acc1 += mi * ((mrow[j0 + 128] != 0) ? 1.0f : 0.0f);
        acc2 += mi * ((mrow[j0 + 256] != 0) ? 1.0f : 0.0f);
    }
    g_count[i * SEQ + j0]       = acc0;
    g_count[i * SEQ + j0 + 128] = acc1;
    g_count[i * SEQ + j0 + 256] = acc2;
}

// ---------------------------------------------------------------------------
// Kernel 3: transpose+split wo -> g_wo[p][cd hi | cd lo]
// ---------------------------------------------------------------------------
__global__ void wo_prep_kernel(const float* __restrict__ wo)
{
    const int p = blockIdx.x;
    for (int k = threadIdx.x; k < 1024; k += 256) {
        float v = wo[(size_t)k * DP + p];
        __nv_bfloat16 h = __float2bfloat16(v);
        __nv_bfloat16 l = __float2bfloat16(v - __bfloat162float(h));
        g_wo[(size_t)p * 2048 + k]        = h;
        g_wo[(size_t)p * 2048 + 1024 + k] = l;
    }
}

// ---------------------------------------------------------------------------
// GEMM1 (mma.sync bf16, cp.async double-buffered, K64 chunks, frag pipeline):
// outer = L' x R'^T.  M=N=12288, K'=768. CTA 128x128, 4 warps, warp 64x64.
// ---------------------------------------------------------------------------
__global__ void __launch_bounds__(128, 2)
gemm1_kernel()
{
    extern __shared__ __align__(16) char dsm[];
    const uint32_t s0 = smem_u32(dsm);

    const int tid  = threadIdx.x;
    const int wid  = tid >> 5;
    const int lane = tid & 31;
    const int warpM = wid & 1;
    const int warpN = wid >> 1;
    const int aRow0 = blockIdx.x * 128;
    const int bRow0 = blockIdx.y * 128;
    const int lj = tid & 7;             // col group for loads
    const int lr = tid >> 3;            // 0..15

    // per-lane fragment base offsets (bytes, within an operand section)
    const uint32_t aFragOff =
        (uint32_t)(((warpM * 64 + (lane & 15)) * SPAD + ((lane >> 4) << 3)) * 2);
    const uint32_t bFragOff =
        (uint32_t)(((warpN * 64 + (lane & 7) + ((lane >> 4) << 3)) * SPAD
                    + (((lane >> 3) & 1) << 3)) * 2);

    float acc[4][8][4];
#pragma unroll
    for (int mt = 0; mt < 4; mt++)
#pragma unroll
        for (int nt = 0; nt < 8; nt++)
#pragma unroll
            for (int e = 0; e < 4; e++) acc[mt][nt][e] = 0.f;

    auto issue = [&](int kc) {
        const int st = kc & 1;
        const int k0 = kc * BK;
        const int colA = (k0 < 256) ? k0 : k0 - 256;
        const int colB = (k0 < 512) ? k0 : k0 - 512;
        const uint32_t sa = s0 + st * STAGEB;
        const uint32_t sb = sa + ABYTES;
#pragma unroll
        for (int q = 0; q < 8; q++) {
            const int r = lr + q * 16;
            cp16(sa + (uint32_t)((r * SPAD + lj * 8) * 2),
                 &g_l[(size_t)(aRow0 + r) * 512 + colA + lj * 8]);
            cp16(sb + (uint32_t)((r * SPAD + lj * 8) * 2),
                 &g_r[(size_t)(bRow0 + r) * 512 + colB + lj * 8]);
        }
        cp_commit();
    };

    uint32_t af[2][4][4], bf_[2][4][4];

    issue(0);
    for (int kc = 0; kc < NK1; kc++) {
        if (kc + 1 < NK1) { issue(kc + 1); cp_wait1(); }
        else              { cp_wait0(); }
        __syncthreads();
        const int st = kc & 1;
        const uint32_t sa = s0 + st * STAGEB;
        const uint32_t sb = sa + ABYTES;

        // preload step 0 fragments
#pragma unroll
        for (int mt = 0; mt < 4; mt++)
            ldmat_x4(af[0][mt], sa + aFragOff + mt * (16 * SPAD * 2));
#pragma unroll
        for (int g = 0; g < 4; g++)
            ldmat_x4(bf_[0][g], sb + bFragOff + g * (16 * SPAD * 2));

#pragma unroll
        for (int ks = 0; ks < 4; ks++) {
            const int cur = ks & 1;
            if (ks < 3) {
                const uint32_t ko = (uint32_t)((ks + 1) * 32);
#pragma unroll
                for (int mt = 0; mt < 4; mt++)
                    ldmat_x4(af[cur ^ 1][mt], sa + aFragOff + mt * (16 * SPAD * 2) + ko);
#pragma unroll
                for (int g = 0; g < 4; g++)
                    ldmat_x4(bf_[cur ^ 1][g], sb + bFragOff + g * (16 * SPAD * 2) + ko);
            }
#pragma unroll
            for (int nt = 0; nt < 8; nt++) {
                const uint32_t b0 = bf_[cur][nt >> 1][(nt & 1) * 2];
                const uint32_t b1 = bf_[cur][nt >> 1][(nt & 1) * 2 + 1];
#pragma unroll
                for (int mt = 0; mt < 4; mt++)
                    mma16816(acc[mt][nt], af[cur][mt], b0, b1);
            }
        }
        __syncthreads();
    }

    // ---- staged epilogue: two passes (hi, lo) through smem ----
    __nv_bfloat16* ep = (__nv_bfloat16*)dsm;
    const int i0 = blockIdx.x * 4;
    const int j0 = blockIdx.y * 4;
#pragma unroll
    for (int half = 0; half < 2; half++) {
        __syncthreads();
#pragma unroll
        for (int mt = 0; mt < 4; mt++)
#pragma unroll
            for (int nt = 0; nt < 8; nt++)
#pragma unroll
                for (int h = 0; h < 2; h++) {
                    const int row  = warpM * 64 + mt * 16 + (lane >> 2) + h * 8;
                    const int colp = warpN * 64 + nt * 8 + (lane & 3) * 2;
                    const float v0 = acc[mt][nt][h * 2 + 0];
                    const float v1 = acc[mt][nt][h * 2 + 1];
                    __nv_bfloat16 x0, x1;
                    if (half == 0) {
                        x0 = __float2bfloat16(v0);
                        x1 = __float2bfloat16(v1);
                    } else {
                        __nv_bfloat16 h0 = __float2bfloat16(v0);
                        __nv_bfloat16 h1 = __float2bfloat16(v1);
                        x0 = __float2bfloat16(v0 - __bfloat162float(h0));
                        x1 = __float2bfloat16(v1 - __bfloat162float(h1));
                    }
                    *(uint32_t*)&ep[row * EP + colp] = pack_bf16(x0, x1);
                }
        __syncthreads();
#pragma unroll
        for (int pp = 0; pp < 4; pp++) {
            const int pr = wid * 4 + pp;
            const int ii = pr >> 2, jj = pr & 3;
            const size_t pair = (size_t)(i0 + ii) * SEQ + (j0 + jj);
#pragma unroll
            for (int it = 0; it < 4; it++) {
                const int t = it * 32 + lane;
                const int c = t >> 2, d8 = (t & 3) * 8;
                uint4 v = *(const uint4*)&ep[(ii * 32 + c) * EP + jj * 32 + d8];
                *(uint4*)&g_outer[pair * 2048 + half * 1024 + c * 32 + d8] = v;
            }
        }
    }
}

// ---------------------------------------------------------------------------
// GEMM2 (mma.sync bf16, cp.async double-buffered, K64 chunks, frag pipeline):
// out = outer x wo^T.  M=147456, N=128, K'=3072. Epilogue: +bo, /(count+eps).
// ---------------------------------------------------------------------------
__global__ void __launch_bounds__(128, 2)
gemm2_kernel(const float* __restrict__ bo, float* __restrict__ out)
{
    extern __shared__ __align__(16) char dsm[];
    const uint32_t s0 = smem_u32(dsm);

    const int tid  = threadIdx.x;
    const int wid  = tid >> 5;
    const int lane = tid & 31;
    const int warpM = wid & 1;
    const int warpN = wid >> 1;
    const size_t pair0 = (size_t)blockIdx.x * 128;
    const int lj = tid & 7;
    const int lr = tid >> 3;

    const uint32_t aFragOff =
        (uint32_t)(((warpM * 64 + (lane & 15)) * SPAD + ((lane >> 4) << 3)) * 2);
    const uint32_t bFragOff =
        (uint32_t)(((warpN * 64 + (lane & 7) + ((lane >> 4) << 3)) * SPAD
                    + (((lane >> 3) & 1) << 3)) * 2);

    float acc[4][8][4];
#pragma unroll
    for (int mt = 0; mt < 4; mt++)
#pragma unroll
        for (int nt = 0; nt < 8; nt++)
#pragma unroll
            for (int e = 0; e < 4; e++) acc[mt][nt][e] = 0.f;

    auto issue = [&](int kc) {
        const int st = kc & 1;
        const int k0 = kc * BK;
        const int colA = (k0 < 1024) ? k0 : k0 - 1024;
        const int colB = (k0 < 2048) ? k0 : k0 - 2048;
        const uint32_t sa = s0 + st * STAGEB;
        const uint32_t sb = sa + ABYTES;
#pragma unroll
        for (int q = 0; q < 8; q++) {
            const int r = lr + q * 16;
            cp16(sa + (uint32_t)((r * SPAD + lj * 8) * 2),
                 &g_outer[(pair0 + r) * 2048 + colA + lj * 8]);
            cp16(sb + (uint32_t)((r * SPAD + lj * 8) * 2),
                 &g_wo[(size_t)r * 2048 + colB + lj * 8]);
        }
        cp_commit();
    };

    uint32_t af[2][4][4], bf_[2][4][4];

    issue(0);
    for (int kc = 0; kc < NK2; kc++) {
        if (kc + 1 < NK2) { issue(kc + 1); cp_wait1(); }
        else              { cp_wait0(); }
        __syncthreads();
        const int st = kc & 1;
        const uint32_t sa = s0 + st * STAGEB;
        const uint32_t sb = sa + ABYTES;

#pragma unroll
        for (int mt = 0; mt < 4; mt++)
            ldmat_x4(af[0][mt], sa + aFragOff + mt * (16 * SPAD * 2));
#pragma unroll
        for (int g = 0; g < 4; g++)
            ldmat_x4(bf_[0][g], sb + bFragOff + g * (16 * SPAD * 2));

#pragma unroll
        for (int ks = 0; ks < 4; ks++) {
            const int cur = ks & 1;
            if (ks < 3) {
                const uint32_t ko = (uint32_t)((ks + 1) * 32);
#pragma unroll
                for (int mt = 0; mt < 4; mt++)
                    ldmat_x4(af[cur ^ 1][mt], sa + aFragOff + mt * (16 * SPAD * 2) + ko);
#pragma unroll
                for (int g = 0; g < 4; g++)
                    ldmat_x4(bf_[cur ^ 1][g], sb + bFragOff + g * (16 * SPAD * 2) + ko);
            }
#pragma unroll
            for (int nt = 0; nt < 8; nt++) {
                const uint32_t b0 = bf_[cur][nt >> 1][(nt & 1) * 2];
                const uint32_t b1 = bf_[cur][nt >> 1][(nt & 1) * 2 + 1];
#pragma unroll
                for (int mt = 0; mt < 4; mt++)
                    mma16816(acc[mt][nt], af[cur][mt], b0, b1);
            }
        }
        __syncthreads();
    }

    // Epilogue: (acc + bo[p]) / (count[pair] + eps)
#pragma unroll
    for (int mt = 0; mt < 4; mt++) {
#pragma unroll
        for (int h = 0; h < 2; h++) {
            const int rA = warpM * 64 + mt * 16 + (lane >> 2) + h * 8;
            const size_t pair = pair0 + rA;
            const float inv = 1.0f / (g_count[pair] + EPSV);
#pragma unroll
            for (int nt = 0; nt < 8; nt++) {
                const int p = warpN * 64 + nt * 8 + (lane & 3) * 2;
                float2 o;
                o.x = (acc[mt][nt][h * 2 + 0] + bo[p])     * inv;
                o.y = (acc[mt][nt][h * 2 + 1] + bo[p + 1]) * inv;
                *(float2*)&out[pair * DP + p] = o;
            }
        }
    }
}

// ---------------------------------------------------------------------------
extern "C" void kernel_launch(void* const* d_in, const int* in_sizes, int n_in,
                              void* d_out, int out_size)
{
    const float* x    = (const float*)d_in[0];
    const int*   mk   = (const int*)d_in[1];
    const float* ln_g = (const float*)d_in[2];
    const float* ln_b = (const float*)d_in[3];
    const float* wl   = (const float*)d_in[4];
    const float* bl   = (const float*)d_in[5];
    const float* wr   = (const float*)d_in[6];
    const float* br   = (const float*)d_in[7];
    const float* wo   = (const float*)d_in[8];
    const float* bo   = (const float*)d_in[9];
    float* out        = (float*)d_out;

    cudaFuncSetAttribute(gemm1_kernel,
                         cudaFuncAttributeMaxDynamicSharedMemorySize, SMEMSZ);
    cudaFuncSetAttribute(gemm2_kernel,
                         cudaFuncAttributeMaxDynamicSharedMemorySize, SMEMSZ);

    ln_proj_kernel<<<SEQ * 8, 64>>>(x, mk, ln_g, ln_b, wl, bl, wr, br);
    count_kernel<<<SEQ, 128>>>(mk);
    wo_prep_kernel<<<DP, 256>>>(wo);
    gemm1_kernel<<<dim3(AROWS / 128, AROWS / 128), 128, SMEMSZ>>>();
    gemm2_kernel<<<PAIRS / 128, 128, SMEMSZ>>>(bo, out);
}